// round 12
// baseline (speedup 1.0000x reference)
#include <cuda_runtime.h>

// ForwardKinematics: B=65536, N=24.
// R11: BPW=8 (12 LDS/joint/warp serves 8 batches -> half the L1 wavefronts
// per batch of R10) + sT/phase C deleted (posed joints stored scalar straight
// from phase B; sJ strictly read-only -> no aliasing). smem 37.9KB -> 6 CTAs/SM.
// Bank math: R batch stride 220 f -> banks 28b%32 distinct over b=0..7.
//            J batch stride 76 f  -> banks 12b%32 distinct.

#define THREADS 128
#define MB 32            // batches per block (8 per warp)
#define BPW 8            // batches per warp

static constexpr int NJ   = 24;
static constexpr int RSTR = 220;   // 216 + 4 pad floats = 55 x 16B
static constexpr int JSTR = 76;    // 72 + 4 pad = 19 x 16B
static constexpr int SMEM_FLOATS = MB * (RSTR + JSTR);
static constexpr int SMEM_BYTES  = SMEM_FLOATS * 4;   // 37888 B -> 6 CTAs/SM

__global__ __launch_bounds__(THREADS, 6)
void fk_kernel(const float* __restrict__ rot,
               const float* __restrict__ jnt,
               float* __restrict__ out_pj,
               float* __restrict__ out_rel)
{
    extern __shared__ float sm[];
    float* sR = sm;                    // [MB][RSTR] local R (read-only after A)
    float* sJ = sR + MB * RSTR;        // [MB][JSTR] joints (read-only after A)

    const int tid  = threadIdx.x;
    const int warp = tid >> 5;
    const int lane = tid & 31;
    const int wb   = warp * BPW;
    const long long gBatch = (long long)blockIdx.x * MB + wb;

    // ---------------- Phase A: float4 loads -> float4 smem stores ----------------
    {
        float4* sR4 = reinterpret_cast<float4*>(sR);       // batch stride 55 f4
        const float4* rot4 = reinterpret_cast<const float4*>(rot) + gBatch * 54;
        #pragma unroll
        for (int it = 0; it < 14; ++it) {                  // 8*54 = 432 float4
            int idx = lane + it * 32;
            if (idx < BPW * 54) {
                int b = wb + idx / 54, rf = idx % 54;
                sR4[b * 55 + rf] = rot4[idx];
            }
        }
        float4* sJ4 = reinterpret_cast<float4*>(sJ);       // batch stride 19 f4
        const float4* jnt4 = reinterpret_cast<const float4*>(jnt) + gBatch * 18;
        #pragma unroll
        for (int it = 0; it < 5; ++it) {                   // 8*18 = 144 float4
            int idx = lane + it * 32;
            if (idx < BPW * 18) {
                int b = wb + idx / 18, rf = idx % 18;
                sJ4[b * 19 + rf] = jnt4[idx];
            }
        }
    }
    __syncwarp();

    // ------- Phase B: sync-free chain walk, 8 batches x 4 rows = 32 lanes -------
    {
        constexpr int PAR[NJ] = {-1,0,0,0,1,2,3,4,5,6,7,8,9,9,9,12,13,14,16,17,18,19,20,21};
        const int  bl     = lane >> 2;          // 0..7 local batch
        const int  b      = wb + bl;
        const int  r      = lane & 3;
        const bool active = (r < 3);
        float ring[6][4];                       // [slot][Rg_r0,Rg_r1,Rg_r2,t_r]
        float jring[6][3];                      // [slot][j0,j1,j2]
        const float* mR = sR + b * RSTR;
        const float* mJ = sJ + b * JSTR;
        float4* relW = reinterpret_cast<float4*>(out_rel) + (gBatch + bl) * 96;
        float*  pjW  = out_pj + (gBatch + bl) * 72;

        #pragma unroll
        for (int i = 0; i < NJ; ++i) {
            float4 v;
            if (active) {
                float row[4];
                const float j0 = mJ[i * 3 + 0];
                const float j1 = mJ[i * 3 + 1];
                const float j2 = mJ[i * 3 + 2];
                if (i == 0) {
                    row[0] = mR[r * 3 + 0];
                    row[1] = mR[r * 3 + 1];
                    row[2] = mR[r * 3 + 2];
                    row[3] = (r == 0) ? j0 : (r == 1) ? j1 : j2;
                } else {
                    const int p  = PAR[i];
                    const int ps = p % 6;
                    const float a0 = ring[ps][0], a1 = ring[ps][1], a2 = ring[ps][2];
                    const float l00 = mR[i*9+0], l01 = mR[i*9+1], l02 = mR[i*9+2];
                    const float l10 = mR[i*9+3], l11 = mR[i*9+4], l12 = mR[i*9+5];
                    const float l20 = mR[i*9+6], l21 = mR[i*9+7], l22 = mR[i*9+8];
                    const float rel0 = j0 - jring[ps][0];
                    const float rel1 = j1 - jring[ps][1];
                    const float rel2 = j2 - jring[ps][2];
                    row[0] = a0 * l00 + a1 * l10 + a2 * l20;
                    row[1] = a0 * l01 + a1 * l11 + a2 * l21;
                    row[2] = a0 * l02 + a1 * l12 + a2 * l22;
                    row[3] = ring[ps][3] + a0 * rel0 + a1 * rel1 + a2 * rel2;
                }
                const int s = i % 6;
                #pragma unroll
                for (int k = 0; k < 4; ++k) ring[s][k] = row[k];
                jring[s][0] = j0; jring[s][1] = j1; jring[s][2] = j2;
                pjW[i * 3 + r] = row[3];                      // posed joint (tiny output)
                v = make_float4(row[0], row[1], row[2],
                                row[3] - (row[0]*j0 + row[1]*j1 + row[2]*j2));
            } else {
                v = make_float4(0.f, 0.f, 0.f, 1.f);          // bottom row
            }
            relW[i * 4 + r] = v;                              // direct rel store
        }
    }
}

extern "C" void kernel_launch(void* const* d_in, const int* in_sizes, int n_in,
                              void* d_out, int out_size)
{
    const float* rot = (const float*)d_in[0];
    const float* jnt = (const float*)d_in[1];
    float* out = (float*)d_out;

    const long long B = 65536;
    float* out_pj  = out;
    float* out_rel = out + (size_t)B * NJ * 3;

    cudaFuncSetAttribute(fk_kernel, cudaFuncAttributeMaxDynamicSharedMemorySize, SMEM_BYTES);

    const int grid = (int)(B / MB);   // 2048 blocks
    fk_kernel<<<grid, THREADS, SMEM_BYTES>>>(rot, jnt, out_pj, out_rel);
}

// round 13
// speedup vs baseline: 1.2048x; 1.2048x over previous
#include <cuda_runtime.h>

// ForwardKinematics: B=65536, N=24.
// R12 = R10 (MB=16, 7 CTAs/SM, sT + coalesced phase C) with phase-B smem reads
// converted to aligned LDS.128 windows + compile-time component extraction:
//   R of joint i  = floats [9i, 9i+9)  -> 3 aligned float4 words, always
//   j of joint i  = floats [3i, 3i+3)  -> 1 or 2 words (constexpr per i)
// 12 scalar LDS/joint -> ~4.5 LDS.128/joint. Batch stride 880B: 112*b mod 128
// distinct over b=0..7 -> conflict-free 128-bit access.

#define THREADS 128
#define MB 16            // batches per block (4 per warp)
#define BPW 4            // batches per warp

static constexpr int NJ   = 24;
static constexpr int RSTR = 220;   // 216 + 4 pad floats = 55 x 16B
static constexpr int JSTR = 76;    // 72 + 4 pad = 19 x 16B
static constexpr int TSTR = 76;    // global t rows
static constexpr int SMEM_FLOATS = MB * (RSTR + JSTR + TSTR);
static constexpr int SMEM_BYTES  = SMEM_FLOATS * 4;   // 23808 B -> 7 CTAs/SM

__global__ __launch_bounds__(THREADS, 7)
void fk_kernel(const float* __restrict__ rot,
               const float* __restrict__ jnt,
               float* __restrict__ out_pj,
               float* __restrict__ out_rel)
{
    extern __shared__ float sm[];
    float* sR = sm;                    // [MB][RSTR] local R (read-only after A)
    float* sJ = sR + MB * RSTR;        // [MB][JSTR] joints (read-only after A)
    float* sT = sJ + MB * JSTR;        // [MB][TSTR] global t

    const int tid  = threadIdx.x;
    const int warp = tid >> 5;
    const int lane = tid & 31;
    const int wb   = warp * BPW;
    const long long gBatch = (long long)blockIdx.x * MB + wb;

    // ---------------- Phase A: float4 loads -> float4 smem stores ----------------
    {
        float4* sR4 = reinterpret_cast<float4*>(sR);       // batch stride 55 f4
        const float4* rot4 = reinterpret_cast<const float4*>(rot) + gBatch * 54;
        #pragma unroll
        for (int it = 0; it < 7; ++it) {                   // 4*54 = 216 float4
            int idx = lane + it * 32;
            if (idx < BPW * 54) {
                int b = wb + idx / 54, rf = idx % 54;
                sR4[b * 55 + rf] = rot4[idx];
            }
        }
        float4* sJ4 = reinterpret_cast<float4*>(sJ);       // batch stride 19 f4
        const float4* jnt4 = reinterpret_cast<const float4*>(jnt) + gBatch * 18;
        #pragma unroll
        for (int it = 0; it < 3; ++it) {                   // 4*18 = 72 float4
            int idx = lane + it * 32;
            if (idx < BPW * 18) {
                int b = wb + idx / 18, rf = idx % 18;
                sJ4[b * 19 + rf] = jnt4[idx];
            }
        }
    }
    __syncwarp();

    // ------- Phase B: chain walk; windowed LDS.128 reads, constexpr extraction -------
    {
        constexpr int PAR[NJ] = {-1,0,0,0,1,2,3,4,5,6,7,8,9,9,9,12,13,14,16,17,18,19,20,21};
        const int  bl     = lane >> 2;          // 0..7; only 0..3 valid
        const int  b      = wb + bl;
        const int  r      = lane & 3;
        const bool inB    = (bl < BPW);
        const bool active = inB && (r < 3);
        float ring[6][4];                       // [slot][Rg_r0,Rg_r1,Rg_r2,t_r]
        float jring[6][3];                      // [slot][j0,j1,j2]
        const float4* mR4 = reinterpret_cast<const float4*>(sR + b * RSTR);
        const float4* mJ4 = reinterpret_cast<const float4*>(sJ + b * JSTR);
        float*        mT  = sT + b * TSTR;
        float4* relW = reinterpret_cast<float4*>(out_rel) + (gBatch + bl) * 96;

        #pragma unroll
        for (int i = 0; i < NJ; ++i) {
            float4 v;
            if (active) {
                // ---- R window: 3 aligned float4 words cover floats [9i, 9i+9) ----
                const int rw  = (9 * i) >> 2;          // constexpr after unroll
                const int ro  = (9 * i) & 3;
                const float4 W0 = mR4[rw + 0];
                const float4 W1 = mR4[rw + 1];
                const float4 W2 = mR4[rw + 2];
                const float rwin[12] = {W0.x, W0.y, W0.z, W0.w,
                                        W1.x, W1.y, W1.z, W1.w,
                                        W2.x, W2.y, W2.z, W2.w};
                const float l00 = rwin[ro+0], l01 = rwin[ro+1], l02 = rwin[ro+2];
                const float l10 = rwin[ro+3], l11 = rwin[ro+4], l12 = rwin[ro+5];
                const float l20 = rwin[ro+6], l21 = rwin[ro+7], l22 = rwin[ro+8];
                // ---- j window: 1-2 aligned words cover floats [3i, 3i+3) ----
                const int jw = (3 * i) >> 2;
                const int jo = (3 * i) & 3;
                const float4 JW0 = mJ4[jw];
                float jwin[8] = {JW0.x, JW0.y, JW0.z, JW0.w, 0.f, 0.f, 0.f, 0.f};
                if (jo > 1) {                           // constexpr: needs second word
                    const float4 JW1 = mJ4[jw + 1];
                    jwin[4] = JW1.x; jwin[5] = JW1.y; jwin[6] = JW1.z; jwin[7] = JW1.w;
                }
                const float j0 = jwin[jo+0], j1 = jwin[jo+1], j2 = jwin[jo+2];

                float row[4];
                if (i == 0) {
                    row[0] = (r == 0) ? l00 : (r == 1) ? l10 : l20;
                    row[1] = (r == 0) ? l01 : (r == 1) ? l11 : l21;
                    row[2] = (r == 0) ? l02 : (r == 1) ? l12 : l22;
                    row[3] = (r == 0) ? j0  : (r == 1) ? j1  : j2;
                } else {
                    const int p  = PAR[i];
                    const int ps = p % 6;
                    const float a0 = ring[ps][0], a1 = ring[ps][1], a2 = ring[ps][2];
                    const float rel0 = j0 - jring[ps][0];
                    const float rel1 = j1 - jring[ps][1];
                    const float rel2 = j2 - jring[ps][2];
                    row[0] = a0 * l00 + a1 * l10 + a2 * l20;
                    row[1] = a0 * l01 + a1 * l11 + a2 * l21;
                    row[2] = a0 * l02 + a1 * l12 + a2 * l22;
                    row[3] = ring[ps][3] + a0 * rel0 + a1 * rel1 + a2 * rel2;
                }
                const int s = i % 6;
                #pragma unroll
                for (int k = 0; k < 4; ++k) ring[s][k] = row[k];
                jring[s][0] = j0; jring[s][1] = j1; jring[s][2] = j2;
                mT[i * 3 + r] = row[3];                       // for posed_joints
                v = make_float4(row[0], row[1], row[2],
                                row[3] - (row[0]*j0 + row[1]*j1 + row[2]*j2));
            } else {
                v = make_float4(0.f, 0.f, 0.f, 1.f);          // bottom row
            }
            if (inB)
                relW[i * 4 + r] = v;                          // direct rel store
        }
    }
    __syncwarp();

    // ---------------- Phase C: coalesced posed-joints copy (LDS.128) ----------------
    {
        const float4* sT4 = reinterpret_cast<const float4*>(sT);   // batch stride 19 f4
        float4* pj4 = reinterpret_cast<float4*>(out_pj) + gBatch * 18;
        #pragma unroll
        for (int it = 0; it < 3; ++it) {                   // 4*18 = 72 float4
            int idx = lane + it * 32;
            if (idx < BPW * 18) {
                int b = wb + idx / 18, rf = idx % 18;
                pj4[idx] = sT4[b * 19 + rf];
            }
        }
    }
}

extern "C" void kernel_launch(void* const* d_in, const int* in_sizes, int n_in,
                              void* d_out, int out_size)
{
    const float* rot = (const float*)d_in[0];
    const float* jnt = (const float*)d_in[1];
    float* out = (float*)d_out;

    const long long B = 65536;
    float* out_pj  = out;
    float* out_rel = out + (size_t)B * NJ * 3;

    cudaFuncSetAttribute(fk_kernel, cudaFuncAttributeMaxDynamicSharedMemorySize, SMEM_BYTES);

    const int grid = (int)(B / MB);   // 4096 blocks
    fk_kernel<<<grid, THREADS, SMEM_BYTES>>>(rot, jnt, out_pj, out_rel);
}